// round 16
// baseline (speedup 1.0000x reference)
#include <cuda_runtime.h>
#include <cuda_bf16.h>
#include <math.h>
#include <cstdint>

#define BB   8
#define NA   4096
#define NAA  1024
#define NPC  4096
#define KNB  16
#define KNC  14
#define GG   32
#define DA   12
#define FF   128
#define DD   128
#define NATTR 39     // NCAT+1
#define APB  8       // atoms per block in atom_kernel
#define GP   33      // padded inner dim of sh_g (bank spread)
#define KM   (GG*DA) // 384
#define SPAD 40      // padded bf16 row stride in gemm smem tiles

// -------- scratch (static device globals; no allocation allowed) ----------
__device__ __nv_bfloat16 g_Mh [BB*NA*KM];   // 25 MB
__device__ __nv_bfloat16 g_Ml [BB*NA*KM];   // 25 MB
__device__ __nv_bfloat16 g_yh [BB*NA*FF];   // 8.4 MB
__device__ __nv_bfloat16 g_yl [BB*NA*FF];   // 8.4 MB
__device__ __nv_bfloat16 g_WnhT[FF*KM];     // W_nem^T hi  (n-major, K=384)
__device__ __nv_bfloat16 g_WnlT[FF*KM];
__device__ __nv_bfloat16 g_WahT[DD*FF];     // W_att^T
__device__ __nv_bfloat16 g_WalT[DD*FF];
__device__ __nv_bfloat16 g_WfhT[DD*FF];     // W_feat^T
__device__ __nv_bfloat16 g_WflT[DD*FF];
__device__ float g_att   [BB*NA*DD];
__device__ float g_feat  [BB*NA*DD];
__device__ float g_masky [BB*NA];
__device__ float g_pooled[BB*NAA*DD];
__device__ float g_mean  [DD];
__device__ float g_invstd[DD];

// -------- packed f32x2 helpers (atom kernel) -------------------------------
__device__ __forceinline__ unsigned long long pk2(float lo, float hi) {
    unsigned long long r;
    asm("mov.b64 %0, {%1, %2};" : "=l"(r) : "f"(lo), "f"(hi));
    return r;
}
__device__ __forceinline__ void fma2(unsigned long long& d,
                                     unsigned long long a,
                                     unsigned long long b) {
    asm("fma.rn.f32x2 %0, %1, %2, %0;" : "+l"(d) : "l"(a), "l"(b));
}
__device__ __forceinline__ float2 upk2(unsigned long long v) {
    float2 f;
    asm("mov.b64 {%0, %1}, %2;" : "=f"(f.x), "=f"(f.y) : "l"(v));
    return f;
}

// -------- warp MMA: m16n8k16 bf16 (sm_80+ baseline feature) ---------------
__device__ __forceinline__ void mma_bf16(float* d, const uint32_t* a,
                                         uint32_t b0, uint32_t b1) {
    asm volatile(
        "mma.sync.aligned.m16n8k16.row.col.f32.bf16.bf16.f32 "
        "{%0,%1,%2,%3}, {%4,%5,%6,%7}, {%8,%9}, {%0,%1,%2,%3};"
        : "+f"(d[0]), "+f"(d[1]), "+f"(d[2]), "+f"(d[3])
        : "r"(a[0]), "r"(a[1]), "r"(a[2]), "r"(a[3]), "r"(b0), "r"(b1));
}

// ==========================================================================
// Kernel A: per-atom stages 0-3. 8 atoms per block, 128 threads.
// Writes M as bf16 hi/lo to gmem.
// ==========================================================================
__global__ __launch_bounds__(128) void atom_kernel(
    const float* __restrict__ pc,
    const float* __restrict__ mask_atom,
    const float* __restrict__ attr_table,
    const float* __restrict__ gauss,
    const int*   __restrict__ frame_idx,
    const int*   __restrict__ attr_idx,
    const int*   __restrict__ nb_idx)
{
    __shared__ float sh_attr [NATTR*DA];
    __shared__ float sh_mattr[NATTR];
    __shared__ float sh_gc   [GG*3];
    __shared__ float sh_R    [APB][9];
    __shared__ float sh_c    [APB][3];
    __shared__ float sh_masky[APB];
    __shared__ __align__(16) float sh_g   [APB][KNB][GP];
    __shared__ __align__(16) float sh_anb [APB][KNB][DA];

    const int t  = threadIdx.x;
    const int ai = t >> 4;
    const int k  = t & 15;
    const long gaBase = (long)blockIdx.x * APB;
    const long ga = gaBase + ai;
    const int  b  = (int)(ga >> 12);

    for (int i = t; i < NATTR*DA; i += 128) sh_attr[i] = attr_table[i];
    for (int i = t; i < GG*3;     i += 128) sh_gc[i]   = gauss[i];
    __syncthreads();

    if (t < NATTR) {
        float any = 0.f;
        #pragma unroll
        for (int a = 0; a < DA; a++) if (sh_attr[t*DA + a] != 0.f) any = 1.f;
        sh_mattr[t] = any;
    }
    if (k == 0) {
        const int* fi = frame_idx + ga*3;
        const float* pb = pc + (long)b*NPC*3;
        int i0 = fi[0], i1 = fi[1], i2 = fi[2];
        float c0 = pb[i1*3+0], c1 = pb[i1*3+1], c2 = pb[i1*3+2];
        float a0 = pb[i2*3+0]-c0, a1 = pb[i2*3+1]-c1, a2 = pb[i2*3+2]-c2;
        float n1 = sqrtf(a0*a0 + a1*a1 + a2*a2);
        float s1 = 1.f / (n1 + 1e-8f);
        float u10 = a0*s1, u11 = a1*s1, u12 = a2*s1;
        float v0 = pb[i0*3+0]-c0, v1 = pb[i0*3+1]-c1, v2 = pb[i0*3+2]-c2;
        float dp = v0*u10 + v1*u11 + v2*u12;
        float w0 = v0 - dp*u10, w1 = v1 - dp*u11, w2 = v2 - dp*u12;
        float n2 = sqrtf(w0*w0 + w1*w1 + w2*w2);
        float s2 = 1.f / (n2 + 1e-8f);
        float u20 = w0*s2, u21 = w1*s2, u22 = w2*s2;
        float u30 = u11*u22 - u12*u21;
        float u31 = u12*u20 - u10*u22;
        float u32 = u10*u21 - u11*u20;
        sh_R[ai][0]=u10; sh_R[ai][1]=u11; sh_R[ai][2]=u12;
        sh_R[ai][3]=u20; sh_R[ai][4]=u21; sh_R[ai][5]=u22;
        sh_R[ai][6]=u30; sh_R[ai][7]=u31; sh_R[ai][8]=u32;
        sh_c[ai][0]=c0;  sh_c[ai][1]=c1;  sh_c[ai][2]=c2;
    }
    __syncthreads();

    if (k == 0) {
        int own = attr_idx[ga];
        sh_masky[ai] = mask_atom[ga] * sh_mattr[own];
    }
    {
        int nb  = nb_idx[ga*KNB + k];
        long nbg = (long)b*NA + nb;
        int fi1 = frame_idx[nbg*3 + 1];
        const float* pb = pc + (long)b*NPC*3;
        float dx = pb[fi1*3+0] - sh_c[ai][0];
        float dy = pb[fi1*3+1] - sh_c[ai][1];
        float dz = pb[fi1*3+2] - sh_c[ai][2];
        float r0 = sh_R[ai][0]*dx + sh_R[ai][1]*dy + sh_R[ai][2]*dz;
        float r1 = sh_R[ai][3]*dx + sh_R[ai][4]*dy + sh_R[ai][5]*dz;
        float r2 = sh_R[ai][6]*dx + sh_R[ai][7]*dy + sh_R[ai][8]*dz;
        #pragma unroll
        for (int gi = 0; gi < GG; gi++) {
            float gx = r0 - sh_gc[gi*3+0];
            float gy = r1 - sh_gc[gi*3+1];
            float gz = r2 - sh_gc[gi*3+2];
            sh_g[ai][k][gi] = __expf(-0.5f * (gx*gx + gy*gy + gz*gz));
        }
        int na = attr_idx[nbg];
        float m = sh_mattr[na];
        #pragma unroll
        for (int a = 0; a < DA; a++)
            sh_anb[ai][k][a] = sh_attr[na*DA + a] * m;
    }
    __syncthreads();

    for (int q = t; q < APB*GG*(DA/4); q += 128) {
        int a2 = q / (GG*(DA/4));
        int r  = q - a2*(GG*(DA/4));
        int gi = r / (DA/4);
        int aq = r - gi*(DA/4);
        unsigned long long acc01 = 0ull, acc23 = 0ull;
        const ulonglong2* anb2 = (const ulonglong2*)&sh_anb[a2][0][0];
        #pragma unroll
        for (int kk = 0; kk < KNB; kk++) {
            float gv = sh_g[a2][kk][gi];
            unsigned long long gg = pk2(gv, gv);
            ulonglong2 av = anb2[kk*(DA/4) + aq];
            fma2(acc01, av.x, gg);
            fma2(acc23, av.y, gg);
        }
        float2 r01 = upk2(acc01), r23 = upk2(acc23);
        float v[4] = { r01.x, r01.y, r23.x, r23.y };
        unsigned short hb[4], lb[4];
        #pragma unroll
        for (int j = 0; j < 4; j++) {
            __nv_bfloat16 h = __float2bfloat16(v[j]);
            __nv_bfloat16 l = __float2bfloat16(v[j] - __bfloat162float(h));
            hb[j] = __bfloat16_as_ushort(h);
            lb[j] = __bfloat16_as_ushort(l);
        }
        long base = (gaBase + a2)*(long)KM + gi*DA + aq*4;
        uint2 hv, lv;
        hv.x = (uint32_t)hb[0] | ((uint32_t)hb[1] << 16);
        hv.y = (uint32_t)hb[2] | ((uint32_t)hb[3] << 16);
        lv.x = (uint32_t)lb[0] | ((uint32_t)lb[1] << 16);
        lv.y = (uint32_t)lb[2] | ((uint32_t)lb[3] << 16);
        *(uint2*)&g_Mh[base] = hv;
        *(uint2*)&g_Ml[base] = lv;
    }
    if (t < APB) g_masky[gaBase + t] = sh_masky[t];
}

// ==========================================================================
// Merged W transpose+split for all three weight matrices (one launch).
// ==========================================================================
__global__ void wsplit_all(const float* __restrict__ Wn,
                           const float* __restrict__ Wa,
                           const float* __restrict__ Wf)
{
    int idx = blockIdx.x*256 + threadIdx.x;
    const float* W;
    __nv_bfloat16 *WhT, *WlT;
    int K, off;
    if (idx < KM*128)                 { W = Wn; WhT = g_WnhT; WlT = g_WnlT; K = KM; off = idx; }
    else if (idx < KM*128 + FF*128)   { W = Wa; WhT = g_WahT; WlT = g_WalT; K = FF; off = idx - KM*128; }
    else if (idx < KM*128 + 2*FF*128) { W = Wf; WhT = g_WfhT; WlT = g_WflT; K = FF; off = idx - KM*128 - FF*128; }
    else return;
    int k = off >> 7, n = off & 127;
    float v = W[off];
    __nv_bfloat16 h = __float2bfloat16(v);
    __nv_bfloat16 l = __float2bfloat16(v - __bfloat162float(h));
    WhT[n*K + k] = h;
    WlT[n*K + k] = l;
}

// ==========================================================================
// GEMM 0 (unchanged from R15 winner): split-bf16 HMMA, BM=BN=128, BK=32.
//   y = (M @ W_nem)/16 * masky (K=384) -> g_yh/g_yl
// ==========================================================================
__global__ __launch_bounds__(256) void gemm_mma0()
{
    constexpr int   K_dim = KM;
    constexpr int   NCH   = K_dim / 32;
    constexpr float smul  = 1.f/16.f;
    const __nv_bfloat16* Ah  = g_Mh;
    const __nv_bfloat16* Al  = g_Ml;
    const __nv_bfloat16* BhT = g_WnhT;
    const __nv_bfloat16* BlT = g_WnlT;

    __shared__ __align__(16) __nv_bfloat16 Ash[128][SPAD];
    __shared__ __align__(16) __nv_bfloat16 Asl[128][SPAD];
    __shared__ __align__(16) __nv_bfloat16 Bsh[128][SPAD];
    __shared__ __align__(16) __nv_bfloat16 Bsl[128][SPAD];

    const int t    = threadIdx.x;
    const int wid  = t >> 5;
    const int lane = t & 31;
    const int g    = lane >> 2;
    const int tig  = lane & 3;
    const int wm   = wid & 3;
    const int wn   = wid >> 2;
    const long rowBase = (long)blockIdx.x * 128;

    float acc[2][8][4];
    #pragma unroll
    for (int mt = 0; mt < 2; mt++)
        #pragma unroll
        for (int nt = 0; nt < 8; nt++)
            #pragma unroll
            for (int d = 0; d < 4; d++) acc[mt][nt][d] = 0.f;

    for (int c = 0; c < NCH; c++) {
        #pragma unroll
        for (int j = 0; j < 2; j++) {
            int idx = j*256 + t;
            int row = idx >> 2;
            int kq  = idx & 3;
            long ga = (rowBase + row)*(long)K_dim + c*32 + kq*8;
            *(uint4*)&Ash[row][kq*8] = *(const uint4*)&Ah[ga];
            *(uint4*)&Asl[row][kq*8] = *(const uint4*)&Al[ga];
            long gb = (long)row*K_dim + c*32 + kq*8;
            *(uint4*)&Bsh[row][kq*8] = *(const uint4*)&BhT[gb];
            *(uint4*)&Bsl[row][kq*8] = *(const uint4*)&BlT[gb];
        }
        __syncthreads();

        #pragma unroll
        for (int ks = 0; ks < 2; ks++) {
            const int k0 = ks*16;
            #pragma unroll
            for (int pass = 0; pass < 3; pass++) {
                const __nv_bfloat16 (*Asm)[SPAD] = (pass == 2) ? Asl : Ash;
                const __nv_bfloat16 (*Bsm)[SPAD] = (pass == 1) ? Bsl : Bsh;
                uint32_t afr[2][4];
                #pragma unroll
                for (int mt = 0; mt < 2; mt++) {
                    int r = 32*wm + 16*mt + g;
                    afr[mt][0] = *(const uint32_t*)&Asm[r  ][k0 + tig*2];
                    afr[mt][1] = *(const uint32_t*)&Asm[r+8][k0 + tig*2];
                    afr[mt][2] = *(const uint32_t*)&Asm[r  ][k0 + tig*2 + 8];
                    afr[mt][3] = *(const uint32_t*)&Asm[r+8][k0 + tig*2 + 8];
                }
                #pragma unroll
                for (int nt = 0; nt < 8; nt++) {
                    int n = 64*wn + nt*8 + g;
                    uint32_t b0 = *(const uint32_t*)&Bsm[n][k0 + tig*2];
                    uint32_t b1 = *(const uint32_t*)&Bsm[n][k0 + tig*2 + 8];
                    mma_bf16(acc[0][nt], afr[0], b0, b1);
                    mma_bf16(acc[1][nt], afr[1], b0, b1);
                }
            }
        }
        __syncthreads();
    }

    #pragma unroll
    for (int mt = 0; mt < 2; mt++) {
        long r0 = rowBase + 32*wm + 16*mt + g;
        long r1 = r0 + 8;
        float sc0 = g_masky[r0]*smul;
        float sc1 = g_masky[r1]*smul;
        #pragma unroll
        for (int nt = 0; nt < 8; nt++) {
            int c0 = 64*wn + nt*8 + tig*2;
            float v00 = acc[mt][nt][0]*sc0, v01 = acc[mt][nt][1]*sc0;
            float v10 = acc[mt][nt][2]*sc1, v11 = acc[mt][nt][3]*sc1;
            __nv_bfloat16 h00 = __float2bfloat16(v00);
            __nv_bfloat16 h01 = __float2bfloat16(v01);
            __nv_bfloat16 h10 = __float2bfloat16(v10);
            __nv_bfloat16 h11 = __float2bfloat16(v11);
            __nv_bfloat16 l00 = __float2bfloat16(v00 - __bfloat162float(h00));
            __nv_bfloat16 l01 = __float2bfloat16(v01 - __bfloat162float(h01));
            __nv_bfloat16 l10 = __float2bfloat16(v10 - __bfloat162float(h10));
            __nv_bfloat16 l11 = __float2bfloat16(v11 - __bfloat162float(h11));
            *(uint32_t*)&g_yh[r0*FF + c0] =
                (uint32_t)__bfloat16_as_ushort(h00) | ((uint32_t)__bfloat16_as_ushort(h01) << 16);
            *(uint32_t*)&g_yl[r0*FF + c0] =
                (uint32_t)__bfloat16_as_ushort(l00) | ((uint32_t)__bfloat16_as_ushort(l01) << 16);
            *(uint32_t*)&g_yh[r1*FF + c0] =
                (uint32_t)__bfloat16_as_ushort(h10) | ((uint32_t)__bfloat16_as_ushort(h11) << 16);
            *(uint32_t*)&g_yl[r1*FF + c0] =
                (uint32_t)__bfloat16_as_ushort(l10) | ((uint32_t)__bfloat16_as_ushort(l11) << 16);
        }
    }
}

// ==========================================================================
// GEMM att+feat fused, small-tile for occupancy. grid = (256, 4):
//   blockIdx.y>>1 : 0=att, 1=feat ; blockIdx.y&1 : column half (64 cols).
// BM=128, BN=64, BK=32. 8 warps as 4x2, warp tile 32x32 (acc 32 floats).
// ==========================================================================
__global__ __launch_bounds__(256) void gemm_att_feat()
{
    const int  mat   = blockIdx.y >> 1;
    const int  nhalf = blockIdx.y & 1;
    const __nv_bfloat16* BhT = mat ? g_WfhT : g_WahT;
    const __nv_bfloat16* BlT = mat ? g_WflT : g_WalT;
    float* C = mat ? g_feat : g_att;
    const int colBase = nhalf * 64;

    __shared__ __align__(16) __nv_bfloat16 Ash[128][SPAD];
    __shared__ __align__(16) __nv_bfloat16 Asl[128][SPAD];
    __shared__ __align__(16) __nv_bfloat16 Bsh[64][SPAD];
    __shared__ __align__(16) __nv_bfloat16 Bsl[64][SPAD];

    const int t    = threadIdx.x;
    const int wid  = t >> 5;
    const int lane = t & 31;
    const int g    = lane >> 2;
    const int tig  = lane & 3;
    const int wm   = wid & 3;        // row 32-tile
    const int wn   = wid >> 2;       // col 32-half
    const long rowBase = (long)blockIdx.x * 128;

    float acc[2][4][4];
    #pragma unroll
    for (int mt = 0; mt < 2; mt++)
        #pragma unroll
        for (int nt = 0; nt < 4; nt++)
            #pragma unroll
            for (int d = 0; d < 4; d++) acc[mt][nt][d] = 0.f;

    for (int c = 0; c < FF/32; c++) {
        // A tiles: 128 rows x 32 k
        #pragma unroll
        for (int j = 0; j < 2; j++) {
            int idx = j*256 + t;
            int row = idx >> 2;
            int kq  = idx & 3;
            long ga = (rowBase + row)*(long)FF + c*32 + kq*8;
            *(uint4*)&Ash[row][kq*8] = *(const uint4*)&g_yh[ga];
            *(uint4*)&Asl[row][kq*8] = *(const uint4*)&g_yl[ga];
        }
        // B tiles: 64 rows x 32 k (one uint4 per thread per tile)
        {
            int brow = t >> 2;
            int bkq  = t & 3;
            long gb = (long)(colBase + brow)*FF + c*32 + bkq*8;
            *(uint4*)&Bsh[brow][bkq*8] = *(const uint4*)&BhT[gb];
            *(uint4*)&Bsl[brow][bkq*8] = *(const uint4*)&BlT[gb];
        }
        __syncthreads();

        #pragma unroll
        for (int ks = 0; ks < 2; ks++) {
            const int k0 = ks*16;
            #pragma unroll
            for (int pass = 0; pass < 3; pass++) {
                const __nv_bfloat16 (*Asm)[SPAD] = (pass == 2) ? Asl : Ash;
                const __nv_bfloat16 (*Bsm)[SPAD] = (pass == 1) ? Bsl : Bsh;
                uint32_t afr[2][4];
                #pragma unroll
                for (int mt = 0; mt < 2; mt++) {
                    int r = 32*wm + 16*mt + g;
                    afr[mt][0] = *(const uint32_t*)&Asm[r  ][k0 + tig*2];
                    afr[mt][1] = *(const uint32_t*)&Asm[r+8][k0 + tig*2];
                    afr[mt][2] = *(const uint32_t*)&Asm[r  ][k0 + tig*2 + 8];
                    afr[mt][3] = *(const uint32_t*)&Asm[r+8][k0 + tig*2 + 8];
                }
                #pragma unroll
                for (int nt = 0; nt < 4; nt++) {
                    int n = 32*wn + nt*8 + g;
                    uint32_t b0 = *(const uint32_t*)&Bsm[n][k0 + tig*2];
                    uint32_t b1 = *(const uint32_t*)&Bsm[n][k0 + tig*2 + 8];
                    mma_bf16(acc[0][nt], afr[0], b0, b1);
                    mma_bf16(acc[1][nt], afr[1], b0, b1);
                }
            }
        }
        __syncthreads();
    }

    // epilogue
    #pragma unroll
    for (int mt = 0; mt < 2; mt++) {
        long r0 = rowBase + 32*wm + 16*mt + g;
        long r1 = r0 + 8;
        float sc0 = g_masky[r0];
        float sc1 = g_masky[r1];
        #pragma unroll
        for (int nt = 0; nt < 4; nt++) {
            int c0 = colBase + 32*wn + nt*8 + tig*2;
            *(float2*)&C[r0*DD + c0] = make_float2(acc[mt][nt][0]*sc0, acc[mt][nt][1]*sc0);
            *(float2*)&C[r1*DD + c0] = make_float2(acc[mt][nt][2]*sc1, acc[mt][nt][3]*sc1);
        }
    }
}

// ==========================================================================
// Kernel B: per-AA softmax pooling.
// ==========================================================================
__global__ __launch_bounds__(128) void aa_kernel(
    const float* __restrict__ mask_aa,
    const int*   __restrict__ seq_idx_atom,
    const int*   __restrict__ seq_idx_aa,
    const int*   __restrict__ aa_nb_idx)
{
    const int t   = threadIdx.x;
    const long g2 = blockIdx.x;
    const int b   = (int)(g2 >> 10);

    __shared__ long  s_idx [KNC];
    __shared__ float s_gate[KNC];
    __shared__ float s_mnb [KNC];

    if (t < KNC) {
        int idx = aa_nb_idx[g2*KNC + t];
        long gi = (long)b*NA + idx;
        s_idx[t] = gi;
        int sn = seq_idx_atom[gi];
        int sa = seq_idx_aa[g2];
        s_gate[t] = (sn == sa) ? 1.f : 0.f;
        s_mnb[t]  = g_masky[gi];
    }
    __syncthreads();

    float l[KNC];
    float mx = -1e30f;
    #pragma unroll
    for (int j = 0; j < KNC; j++) {
        float v = (s_mnb[j] > 0.f) ? g_att[s_idx[j]*DD + t] : -1e9f;
        l[j] = v;
        mx = fmaxf(mx, v);
    }
    float E = 0.f;
    #pragma unroll
    for (int j = 0; j < KNC; j++) {
        l[j] = __expf(l[j] - mx);
        E += l[j];
    }
    float invE = 1.f / E;
    float wsum = 0.f;
    #pragma unroll
    for (int j = 0; j < KNC; j++) {
        float w = l[j] * invE * s_gate[j] * s_mnb[j];
        l[j] = w;
        wsum += w;
    }
    float p = 0.f;
    #pragma unroll
    for (int j = 0; j < KNC; j++)
        p += l[j] * g_feat[s_idx[j]*DD + t];
    p = p / (wsum + 1e-8f) * mask_aa[g2];
    g_pooled[g2*DD + t] = p;
}

// ==========================================================================
// Kernel C: per-channel masked mean/var.
// ==========================================================================
__global__ __launch_bounds__(256) void stats_kernel(const float* __restrict__ mask_aa)
{
    const int d = blockIdx.x;
    const int t = threadIdx.x;
    float s1 = 0.f, s2 = 0.f, sm = 0.f;
    for (int r = t; r < BB*NAA; r += 256) {
        float m = mask_aa[r];
        float p = g_pooled[(long)r*DD + d];
        s1 += m*p; s2 += m*p*p; sm += m;
    }
    __shared__ float r1[256], r2[256], rm[256];
    r1[t] = s1; r2[t] = s2; rm[t] = sm;
    __syncthreads();
    for (int o = 128; o > 0; o >>= 1) {
        if (t < o) { r1[t] += r1[t+o]; r2[t] += r2[t+o]; rm[t] += rm[t+o]; }
        __syncthreads();
    }
    if (t == 0) {
        float n    = rm[0] + 1e-8f;
        float mean = r1[0] / n;
        float var  = (r2[0] - 2.f*mean*r1[0] + mean*mean*rm[0]) / n;
        g_mean[d]   = mean;
        g_invstd[d] = rsqrtf(var + 1e-5f);
    }
}

// ==========================================================================
// Kernel D: batchnorm affine + relu + write both outputs.
// ==========================================================================
__global__ __launch_bounds__(128) void final_kernel(
    const float* __restrict__ mask_aa,
    const float* __restrict__ bn_gamma,
    const float* __restrict__ bn_beta,
    float* __restrict__ out)
{
    const int t   = threadIdx.x;
    const long g2 = blockIdx.x;
    float m = mask_aa[g2];
    float p = g_pooled[g2*DD + t];
    float o = bn_gamma[t] * (p - g_mean[t]) * g_invstd[t] + bn_beta[t];
    o = fmaxf(o * m, 0.f);
    out[g2*DD + t] = o;
    if (t == 0) out[(long)BB*NAA*DD + g2] = m;
}

// ==========================================================================
extern "C" void kernel_launch(void* const* d_in, const int* in_sizes, int n_in,
                              void* d_out, int out_size)
{
    const float* pc        = (const float*)d_in[0];
    const float* mask_atom = (const float*)d_in[1];
    const float* mask_aa   = (const float*)d_in[2];
    const float* attr      = (const float*)d_in[3];
    const float* gauss     = (const float*)d_in[4];
    const float* wnem      = (const float*)d_in[5];
    const float* watt      = (const float*)d_in[6];
    const float* wfeat     = (const float*)d_in[7];
    const float* gamma     = (const float*)d_in[8];
    const float* beta      = (const float*)d_in[9];
    const int*   fidx      = (const int*)d_in[10];
    const int*   aidx      = (const int*)d_in[11];
    const int*   nbidx     = (const int*)d_in[12];
    const int*   seqa      = (const int*)d_in[13];
    const int*   seqaa     = (const int*)d_in[14];
    const int*   aanb      = (const int*)d_in[15];
    float* out = (float*)d_out;

    atom_kernel<<<BB*NA/APB, 128>>>(pc, mask_atom, attr, gauss,
                                    fidx, aidx, nbidx);
    wsplit_all<<<(KM*128 + 2*FF*128 + 255)/256, 256>>>(wnem, watt, wfeat);
    gemm_mma0<<<BB*NA/128, 256>>>();
    {
        dim3 grid(BB*NA/128, 4);
        gemm_att_feat<<<grid, 256>>>();
    }
    aa_kernel<<<BB*NAA, 128>>>(mask_aa, seqa, seqaa, aanb);
    stats_kernel<<<DD, 256>>>(mask_aa);
    final_kernel<<<BB*NAA, 128>>>(mask_aa, gamma, beta, out);
}

// round 17
// speedup vs baseline: 1.0611x; 1.0611x over previous
#include <cuda_runtime.h>
#include <cuda_bf16.h>
#include <math.h>
#include <cstdint>

#define BB   8
#define NA   4096
#define NAA  1024
#define NPC  4096
#define KNB  16
#define KNC  14
#define GG   32
#define DA   12
#define FF   128
#define DD   128
#define NATTR 39     // NCAT+1
#define APB  8       // atoms per block in atom_kernel
#define GP   33      // padded inner dim of sh_g (bank spread)
#define KM   (GG*DA) // 384
#define SPAD 40      // padded bf16 row stride in gemm smem tiles

// -------- scratch (static device globals; no allocation allowed) ----------
__device__ __nv_bfloat16 g_Mh [BB*NA*KM];   // 25 MB
__device__ __nv_bfloat16 g_Ml [BB*NA*KM];   // 25 MB
__device__ __nv_bfloat16 g_yh [BB*NA*FF];   // 8.4 MB
__device__ __nv_bfloat16 g_yl [BB*NA*FF];   // 8.4 MB
__device__ __nv_bfloat16 g_WnhT[FF*KM];     // W_nem^T hi  (n-major, K=384)
__device__ __nv_bfloat16 g_WnlT[FF*KM];
__device__ __nv_bfloat16 g_WahT[DD*FF];     // W_att^T
__device__ __nv_bfloat16 g_WalT[DD*FF];
__device__ __nv_bfloat16 g_WfhT[DD*FF];     // W_feat^T
__device__ __nv_bfloat16 g_WflT[DD*FF];
__device__ float g_att   [BB*NA*DD];
__device__ float g_feat  [BB*NA*DD];
__device__ float g_masky [BB*NA];
__device__ float g_pooled[BB*NAA*DD];
__device__ float g_s1[DD];
__device__ float g_s2[DD];
__device__ float g_sm;

// -------- packed f32x2 helpers (atom kernel) -------------------------------
__device__ __forceinline__ unsigned long long pk2(float lo, float hi) {
    unsigned long long r;
    asm("mov.b64 %0, {%1, %2};" : "=l"(r) : "f"(lo), "f"(hi));
    return r;
}
__device__ __forceinline__ void fma2(unsigned long long& d,
                                     unsigned long long a,
                                     unsigned long long b) {
    asm("fma.rn.f32x2 %0, %1, %2, %0;" : "+l"(d) : "l"(a), "l"(b));
}
__device__ __forceinline__ float2 upk2(unsigned long long v) {
    float2 f;
    asm("mov.b64 {%0, %1}, %2;" : "=f"(f.x), "=f"(f.y) : "l"(v));
    return f;
}

// -------- warp MMA: m16n8k16 bf16 (sm_80+ baseline feature) ---------------
__device__ __forceinline__ void mma_bf16(float* d, const uint32_t* a,
                                         uint32_t b0, uint32_t b1) {
    asm volatile(
        "mma.sync.aligned.m16n8k16.row.col.f32.bf16.bf16.f32 "
        "{%0,%1,%2,%3}, {%4,%5,%6,%7}, {%8,%9}, {%0,%1,%2,%3};"
        : "+f"(d[0]), "+f"(d[1]), "+f"(d[2]), "+f"(d[3])
        : "r"(a[0]), "r"(a[1]), "r"(a[2]), "r"(a[3]), "r"(b0), "r"(b1));
}

// ==========================================================================
// Kernel A: per-atom stages 0-3. 8 atoms per block, 128 threads.
// Writes M as bf16 hi/lo to gmem.
// ==========================================================================
__global__ __launch_bounds__(128) void atom_kernel(
    const float* __restrict__ pc,
    const float* __restrict__ mask_atom,
    const float* __restrict__ attr_table,
    const float* __restrict__ gauss,
    const int*   __restrict__ frame_idx,
    const int*   __restrict__ attr_idx,
    const int*   __restrict__ nb_idx)
{
    __shared__ float sh_attr [NATTR*DA];
    __shared__ float sh_mattr[NATTR];
    __shared__ float sh_gc   [GG*3];
    __shared__ float sh_R    [APB][9];
    __shared__ float sh_c    [APB][3];
    __shared__ float sh_masky[APB];
    __shared__ __align__(16) float sh_g   [APB][KNB][GP];
    __shared__ __align__(16) float sh_anb [APB][KNB][DA];

    const int t  = threadIdx.x;
    const int ai = t >> 4;
    const int k  = t & 15;
    const long gaBase = (long)blockIdx.x * APB;
    const long ga = gaBase + ai;
    const int  b  = (int)(ga >> 12);

    for (int i = t; i < NATTR*DA; i += 128) sh_attr[i] = attr_table[i];
    for (int i = t; i < GG*3;     i += 128) sh_gc[i]   = gauss[i];
    __syncthreads();

    if (t < NATTR) {
        float any = 0.f;
        #pragma unroll
        for (int a = 0; a < DA; a++) if (sh_attr[t*DA + a] != 0.f) any = 1.f;
        sh_mattr[t] = any;
    }
    if (k == 0) {
        const int* fi = frame_idx + ga*3;
        const float* pb = pc + (long)b*NPC*3;
        int i0 = fi[0], i1 = fi[1], i2 = fi[2];
        float c0 = pb[i1*3+0], c1 = pb[i1*3+1], c2 = pb[i1*3+2];
        float a0 = pb[i2*3+0]-c0, a1 = pb[i2*3+1]-c1, a2 = pb[i2*3+2]-c2;
        float n1 = sqrtf(a0*a0 + a1*a1 + a2*a2);
        float s1 = 1.f / (n1 + 1e-8f);
        float u10 = a0*s1, u11 = a1*s1, u12 = a2*s1;
        float v0 = pb[i0*3+0]-c0, v1 = pb[i0*3+1]-c1, v2 = pb[i0*3+2]-c2;
        float dp = v0*u10 + v1*u11 + v2*u12;
        float w0 = v0 - dp*u10, w1 = v1 - dp*u11, w2 = v2 - dp*u12;
        float n2 = sqrtf(w0*w0 + w1*w1 + w2*w2);
        float s2 = 1.f / (n2 + 1e-8f);
        float u20 = w0*s2, u21 = w1*s2, u22 = w2*s2;
        float u30 = u11*u22 - u12*u21;
        float u31 = u12*u20 - u10*u22;
        float u32 = u10*u21 - u11*u20;
        sh_R[ai][0]=u10; sh_R[ai][1]=u11; sh_R[ai][2]=u12;
        sh_R[ai][3]=u20; sh_R[ai][4]=u21; sh_R[ai][5]=u22;
        sh_R[ai][6]=u30; sh_R[ai][7]=u31; sh_R[ai][8]=u32;
        sh_c[ai][0]=c0;  sh_c[ai][1]=c1;  sh_c[ai][2]=c2;
    }
    __syncthreads();

    if (k == 0) {
        int own = attr_idx[ga];
        sh_masky[ai] = mask_atom[ga] * sh_mattr[own];
    }
    {
        int nb  = nb_idx[ga*KNB + k];
        long nbg = (long)b*NA + nb;
        int fi1 = frame_idx[nbg*3 + 1];
        const float* pb = pc + (long)b*NPC*3;
        float dx = pb[fi1*3+0] - sh_c[ai][0];
        float dy = pb[fi1*3+1] - sh_c[ai][1];
        float dz = pb[fi1*3+2] - sh_c[ai][2];
        float r0 = sh_R[ai][0]*dx + sh_R[ai][1]*dy + sh_R[ai][2]*dz;
        float r1 = sh_R[ai][3]*dx + sh_R[ai][4]*dy + sh_R[ai][5]*dz;
        float r2 = sh_R[ai][6]*dx + sh_R[ai][7]*dy + sh_R[ai][8]*dz;
        #pragma unroll
        for (int gi = 0; gi < GG; gi++) {
            float gx = r0 - sh_gc[gi*3+0];
            float gy = r1 - sh_gc[gi*3+1];
            float gz = r2 - sh_gc[gi*3+2];
            sh_g[ai][k][gi] = __expf(-0.5f * (gx*gx + gy*gy + gz*gz));
        }
        int na = attr_idx[nbg];
        float m = sh_mattr[na];
        #pragma unroll
        for (int a = 0; a < DA; a++)
            sh_anb[ai][k][a] = sh_attr[na*DA + a] * m;
    }
    __syncthreads();

    for (int q = t; q < APB*GG*(DA/4); q += 128) {
        int a2 = q / (GG*(DA/4));
        int r  = q - a2*(GG*(DA/4));
        int gi = r / (DA/4);
        int aq = r - gi*(DA/4);
        unsigned long long acc01 = 0ull, acc23 = 0ull;
        const ulonglong2* anb2 = (const ulonglong2*)&sh_anb[a2][0][0];
        #pragma unroll
        for (int kk = 0; kk < KNB; kk++) {
            float gv = sh_g[a2][kk][gi];
            unsigned long long gg = pk2(gv, gv);
            ulonglong2 av = anb2[kk*(DA/4) + aq];
            fma2(acc01, av.x, gg);
            fma2(acc23, av.y, gg);
        }
        float2 r01 = upk2(acc01), r23 = upk2(acc23);
        float v[4] = { r01.x, r01.y, r23.x, r23.y };
        unsigned short hb[4], lb[4];
        #pragma unroll
        for (int j = 0; j < 4; j++) {
            __nv_bfloat16 h = __float2bfloat16(v[j]);
            __nv_bfloat16 l = __float2bfloat16(v[j] - __bfloat162float(h));
            hb[j] = __bfloat16_as_ushort(h);
            lb[j] = __bfloat16_as_ushort(l);
        }
        long base = (gaBase + a2)*(long)KM + gi*DA + aq*4;
        uint2 hv, lv;
        hv.x = (uint32_t)hb[0] | ((uint32_t)hb[1] << 16);
        hv.y = (uint32_t)hb[2] | ((uint32_t)hb[3] << 16);
        lv.x = (uint32_t)lb[0] | ((uint32_t)lb[1] << 16);
        lv.y = (uint32_t)lb[2] | ((uint32_t)lb[3] << 16);
        *(uint2*)&g_Mh[base] = hv;
        *(uint2*)&g_Ml[base] = lv;
    }
    if (t < APB) g_masky[gaBase + t] = sh_masky[t];
}

// ==========================================================================
// Merged W transpose+split (one launch) + zeroing of stats accumulators.
// ==========================================================================
__global__ void wsplit_all(const float* __restrict__ Wn,
                           const float* __restrict__ Wa,
                           const float* __restrict__ Wf)
{
    int idx = blockIdx.x*256 + threadIdx.x;
    if (idx < DD) { g_s1[idx] = 0.f; g_s2[idx] = 0.f; }
    if (idx == 0) g_sm = 0.f;
    const float* W;
    __nv_bfloat16 *WhT, *WlT;
    int K, off;
    if (idx < KM*128)                 { W = Wn; WhT = g_WnhT; WlT = g_WnlT; K = KM; off = idx; }
    else if (idx < KM*128 + FF*128)   { W = Wa; WhT = g_WahT; WlT = g_WalT; K = FF; off = idx - KM*128; }
    else if (idx < KM*128 + 2*FF*128) { W = Wf; WhT = g_WfhT; WlT = g_WflT; K = FF; off = idx - KM*128 - FF*128; }
    else return;
    int k = off >> 7, n = off & 127;
    float v = W[off];
    __nv_bfloat16 h = __float2bfloat16(v);
    __nv_bfloat16 l = __float2bfloat16(v - __bfloat162float(h));
    WhT[n*K + k] = h;
    WlT[n*K + k] = l;
}

// ==========================================================================
// Split-bf16 GEMM on mma.sync (HMMA). 256 thr / 8 warps, BM=BN=128, BK=32.
// (exact R15 winner)
// ==========================================================================
template<int MODE>
__global__ __launch_bounds__(256) void gemm_mma()
{
    constexpr int   K_dim = (MODE == 0) ? KM : FF;
    constexpr int   NCH   = K_dim / 32;
    constexpr float smul  = (MODE == 0) ? (1.f/16.f) : 1.f;
    const __nv_bfloat16* Ah  = (MODE == 0) ? g_Mh : g_yh;
    const __nv_bfloat16* Al  = (MODE == 0) ? g_Ml : g_yl;
    const __nv_bfloat16* BhT = (MODE == 0) ? g_WnhT : (MODE == 1 ? g_WahT : g_WfhT);
    const __nv_bfloat16* BlT = (MODE == 0) ? g_WnlT : (MODE == 1 ? g_WalT : g_WflT);

    __shared__ __align__(16) __nv_bfloat16 Ash[128][SPAD];
    __shared__ __align__(16) __nv_bfloat16 Asl[128][SPAD];
    __shared__ __align__(16) __nv_bfloat16 Bsh[128][SPAD];
    __shared__ __align__(16) __nv_bfloat16 Bsl[128][SPAD];

    const int t    = threadIdx.x;
    const int wid  = t >> 5;
    const int lane = t & 31;
    const int g    = lane >> 2;
    const int tig  = lane & 3;
    const int wm   = wid & 3;
    const int wn   = wid >> 2;
    const long rowBase = (long)blockIdx.x * 128;

    float acc[2][8][4];
    #pragma unroll
    for (int mt = 0; mt < 2; mt++)
        #pragma unroll
        for (int nt = 0; nt < 8; nt++)
            #pragma unroll
            for (int d = 0; d < 4; d++) acc[mt][nt][d] = 0.f;

    for (int c = 0; c < NCH; c++) {
        #pragma unroll
        for (int j = 0; j < 2; j++) {
            int idx = j*256 + t;
            int row = idx >> 2;
            int kq  = idx & 3;
            long ga = (rowBase + row)*(long)K_dim + c*32 + kq*8;
            *(uint4*)&Ash[row][kq*8] = *(const uint4*)&Ah[ga];
            *(uint4*)&Asl[row][kq*8] = *(const uint4*)&Al[ga];
            long gb = (long)row*K_dim + c*32 + kq*8;
            *(uint4*)&Bsh[row][kq*8] = *(const uint4*)&BhT[gb];
            *(uint4*)&Bsl[row][kq*8] = *(const uint4*)&BlT[gb];
        }
        __syncthreads();

        #pragma unroll
        for (int ks = 0; ks < 2; ks++) {
            const int k0 = ks*16;
            #pragma unroll
            for (int pass = 0; pass < 3; pass++) {
                const __nv_bfloat16 (*Asm)[SPAD] = (pass == 2) ? Asl : Ash;
                const __nv_bfloat16 (*Bsm)[SPAD] = (pass == 1) ? Bsl : Bsh;
                uint32_t afr[2][4];
                #pragma unroll
                for (int mt = 0; mt < 2; mt++) {
                    int r = 32*wm + 16*mt + g;
                    afr[mt][0] = *(const uint32_t*)&Asm[r  ][k0 + tig*2];
                    afr[mt][1] = *(const uint32_t*)&Asm[r+8][k0 + tig*2];
                    afr[mt][2] = *(const uint32_t*)&Asm[r  ][k0 + tig*2 + 8];
                    afr[mt][3] = *(const uint32_t*)&Asm[r+8][k0 + tig*2 + 8];
                }
                #pragma unroll
                for (int nt = 0; nt < 8; nt++) {
                    int n = 64*wn + nt*8 + g;
                    uint32_t b0 = *(const uint32_t*)&Bsm[n][k0 + tig*2];
                    uint32_t b1 = *(const uint32_t*)&Bsm[n][k0 + tig*2 + 8];
                    mma_bf16(acc[0][nt], afr[0], b0, b1);
                    mma_bf16(acc[1][nt], afr[1], b0, b1);
                }
            }
        }
        __syncthreads();
    }

    #pragma unroll
    for (int mt = 0; mt < 2; mt++) {
        long r0 = rowBase + 32*wm + 16*mt + g;
        long r1 = r0 + 8;
        float sc0 = g_masky[r0]*smul;
        float sc1 = g_masky[r1]*smul;
        #pragma unroll
        for (int nt = 0; nt < 8; nt++) {
            int c0 = 64*wn + nt*8 + tig*2;
            float v00 = acc[mt][nt][0]*sc0, v01 = acc[mt][nt][1]*sc0;
            float v10 = acc[mt][nt][2]*sc1, v11 = acc[mt][nt][3]*sc1;
            if (MODE == 0) {
                __nv_bfloat16 h00 = __float2bfloat16(v00);
                __nv_bfloat16 h01 = __float2bfloat16(v01);
                __nv_bfloat16 h10 = __float2bfloat16(v10);
                __nv_bfloat16 h11 = __float2bfloat16(v11);
                __nv_bfloat16 l00 = __float2bfloat16(v00 - __bfloat162float(h00));
                __nv_bfloat16 l01 = __float2bfloat16(v01 - __bfloat162float(h01));
                __nv_bfloat16 l10 = __float2bfloat16(v10 - __bfloat162float(h10));
                __nv_bfloat16 l11 = __float2bfloat16(v11 - __bfloat162float(h11));
                *(uint32_t*)&g_yh[r0*FF + c0] =
                    (uint32_t)__bfloat16_as_ushort(h00) | ((uint32_t)__bfloat16_as_ushort(h01) << 16);
                *(uint32_t*)&g_yl[r0*FF + c0] =
                    (uint32_t)__bfloat16_as_ushort(l00) | ((uint32_t)__bfloat16_as_ushort(l01) << 16);
                *(uint32_t*)&g_yh[r1*FF + c0] =
                    (uint32_t)__bfloat16_as_ushort(h10) | ((uint32_t)__bfloat16_as_ushort(h11) << 16);
                *(uint32_t*)&g_yl[r1*FF + c0] =
                    (uint32_t)__bfloat16_as_ushort(l10) | ((uint32_t)__bfloat16_as_ushort(l11) << 16);
            } else {
                float* C = (MODE == 1) ? g_att : g_feat;
                *(float2*)&C[r0*DD + c0] = make_float2(v00, v01);
                *(float2*)&C[r1*DD + c0] = make_float2(v10, v11);
            }
        }
    }
}

// ==========================================================================
// Kernel B: per-AA softmax pooling.
// ==========================================================================
__global__ __launch_bounds__(128) void aa_kernel(
    const float* __restrict__ mask_aa,
    const int*   __restrict__ seq_idx_atom,
    const int*   __restrict__ seq_idx_aa,
    const int*   __restrict__ aa_nb_idx)
{
    const int t   = threadIdx.x;
    const long g2 = blockIdx.x;
    const int b   = (int)(g2 >> 10);

    __shared__ long  s_idx [KNC];
    __shared__ float s_gate[KNC];
    __shared__ float s_mnb [KNC];

    if (t < KNC) {
        int idx = aa_nb_idx[g2*KNC + t];
        long gi = (long)b*NA + idx;
        s_idx[t] = gi;
        int sn = seq_idx_atom[gi];
        int sa = seq_idx_aa[g2];
        s_gate[t] = (sn == sa) ? 1.f : 0.f;
        s_mnb[t]  = g_masky[gi];
    }
    __syncthreads();

    float l[KNC];
    float mx = -1e30f;
    #pragma unroll
    for (int j = 0; j < KNC; j++) {
        float v = (s_mnb[j] > 0.f) ? g_att[s_idx[j]*DD + t] : -1e9f;
        l[j] = v;
        mx = fmaxf(mx, v);
    }
    float E = 0.f;
    #pragma unroll
    for (int j = 0; j < KNC; j++) {
        l[j] = __expf(l[j] - mx);
        E += l[j];
    }
    float invE = 1.f / E;
    float wsum = 0.f;
    #pragma unroll
    for (int j = 0; j < KNC; j++) {
        float w = l[j] * invE * s_gate[j] * s_mnb[j];
        l[j] = w;
        wsum += w;
    }
    float p = 0.f;
    #pragma unroll
    for (int j = 0; j < KNC; j++)
        p += l[j] * g_feat[s_idx[j]*DD + t];
    p = p / (wsum + 1e-8f) * mask_aa[g2];
    g_pooled[g2*DD + t] = p;
}

// ==========================================================================
// Kernel C: coalesced partial stats, atomic accumulate into g_s1/g_s2/g_sm.
// 256 blocks x 256 thr; block handles 32 rows; thread: ch = t&127, half = t>>7.
// ==========================================================================
__global__ __launch_bounds__(256) void stats_part(const float* __restrict__ mask_aa)
{
    const int t    = threadIdx.x;
    const int ch   = t & 127;
    const int half = t >> 7;
    const int base = blockIdx.x * 32;

    float s1 = 0.f, s2 = 0.f, sm = 0.f;
    #pragma unroll
    for (int i = 0; i < 16; i++) {
        int r = base + half + 2*i;
        float m = mask_aa[r];
        float p = g_pooled[(long)r*DD + ch];
        s1 += m*p;
        s2 += m*p*p;
        if (ch == 0) sm += m;
    }

    __shared__ float sh1[2][DD], sh2[2][DD], shm[2];
    sh1[half][ch] = s1;
    sh2[half][ch] = s2;
    if (ch == 0) shm[half] = sm;
    __syncthreads();
    if (t < DD) {
        atomicAdd(&g_s1[t], sh1[0][t] + sh1[1][t]);
        atomicAdd(&g_s2[t], sh2[0][t] + sh2[1][t]);
    }
    if (t == 0) atomicAdd(&g_sm, shm[0] + shm[1]);
}

// ==========================================================================
// Kernel D: batchnorm affine + relu + outputs. 1024 blocks x 256 thr.
// Thread: row = blockIdx.x*8 + (t>>5), channels (t&31)*4 .. +3 (float4).
// mean/invstd computed locally from global sums (cheap, redundant).
// ==========================================================================
__global__ __launch_bounds__(256) void final_kernel(
    const float* __restrict__ mask_aa,
    const float* __restrict__ bn_gamma,
    const float* __restrict__ bn_beta,
    float* __restrict__ out)
{
    const int t   = threadIdx.x;
    const long r  = (long)blockIdx.x*8 + (t >> 5);
    const int c0  = (t & 31) * 4;

    const float n  = g_sm + 1e-8f;
    const float invn = 1.f / n;
    float4 s1 = *(const float4*)&g_s1[c0];
    float4 s2 = *(const float4*)&g_s2[c0];
    float4 ga = *(const float4*)&bn_gamma[c0];
    float4 be = *(const float4*)&bn_beta[c0];
    float mean0 = s1.x*invn, mean1 = s1.y*invn, mean2 = s1.z*invn, mean3 = s1.w*invn;
    float var0 = (s2.x - 2.f*mean0*s1.x + mean0*mean0*g_sm)*invn;
    float var1 = (s2.y - 2.f*mean1*s1.y + mean1*mean1*g_sm)*invn;
    float var2 = (s2.z - 2.f*mean2*s1.z + mean2*mean2*g_sm)*invn;
    float var3 = (s2.w - 2.f*mean3*s1.w + mean3*mean3*g_sm)*invn;
    float is0 = rsqrtf(var0 + 1e-5f);
    float is1 = rsqrtf(var1 + 1e-5f);
    float is2 = rsqrtf(var2 + 1e-5f);
    float is3 = rsqrtf(var3 + 1e-5f);

    float m = mask_aa[r];
    float4 p = *(const float4*)&g_pooled[r*DD + c0];
    float4 o;
    o.x = fmaxf((ga.x*(p.x - mean0)*is0 + be.x) * m, 0.f);
    o.y = fmaxf((ga.y*(p.y - mean1)*is1 + be.y) * m, 0.f);
    o.z = fmaxf((ga.z*(p.z - mean2)*is2 + be.z) * m, 0.f);
    o.w = fmaxf((ga.w*(p.w - mean3)*is3 + be.w) * m, 0.f);
    *(float4*)&out[r*DD + c0] = o;
    if (t < 8) {
        long r2 = (long)blockIdx.x*8 + t;
        out[(long)BB*NAA*DD + r2] = mask_aa[r2];
    }
}

// ==========================================================================
extern "C" void kernel_launch(void* const* d_in, const int* in_sizes, int n_in,
                              void* d_out, int out_size)
{
    const float* pc        = (const float*)d_in[0];
    const float* mask_atom = (const float*)d_in[1];
    const float* mask_aa   = (const float*)d_in[2];
    const float* attr      = (const float*)d_in[3];
    const float* gauss     = (const float*)d_in[4];
    const float* wnem      = (const float*)d_in[5];
    const float* watt      = (const float*)d_in[6];
    const float* wfeat     = (const float*)d_in[7];
    const float* gamma     = (const float*)d_in[8];
    const float* beta      = (const float*)d_in[9];
    const int*   fidx      = (const int*)d_in[10];
    const int*   aidx      = (const int*)d_in[11];
    const int*   nbidx     = (const int*)d_in[12];
    const int*   seqa      = (const int*)d_in[13];
    const int*   seqaa     = (const int*)d_in[14];
    const int*   aanb      = (const int*)d_in[15];
    float* out = (float*)d_out;

    atom_kernel<<<BB*NA/APB, 128>>>(pc, mask_atom, attr, gauss,
                                    fidx, aidx, nbidx);
    wsplit_all<<<(KM*128 + 2*FF*128 + 255)/256, 256>>>(wnem, watt, wfeat);
    gemm_mma<0><<<BB*NA/128, 256>>>();
    gemm_mma<1><<<BB*NA/128, 256>>>();
    gemm_mma<2><<<BB*NA/128, 256>>>();
    aa_kernel<<<BB*NAA, 128>>>(mask_aa, seqa, seqaa, aanb);
    stats_part<<<BB*NAA/32, 256>>>(mask_aa);
    final_kernel<<<BB*NAA/8, 256>>>(mask_aa, gamma, beta, out);
}